// round 1
// baseline (speedup 1.0000x reference)
#include <cuda_runtime.h>
#include <cuda_bf16.h>
#include <cstdint>

#define N_NODES 100000
#define N_EDGES 320000
#define DIM 256

// ---------------- scratch (no allocations allowed) ----------------
__device__ int   g_deg_out[N_NODES];
__device__ int   g_deg_in[N_NODES];
__device__ float g_inv_out[N_NODES];   // out_deg^-0.5 (src-side norm)
__device__ float g_inv_in[N_NODES];    // in_deg^-0.5  (dst-side norm)
__device__ float g_agg[(size_t)N_NODES * DIM];
__device__ float g_h[(size_t)N_NODES * DIM];

// ---------------- kernels ----------------

__global__ void k_init_counts() {
    int i = blockIdx.x * blockDim.x + threadIdx.x;
    if (i < N_NODES) { g_deg_out[i] = 0; g_deg_in[i] = 0; }
}

__global__ void k_count_deg(const int* __restrict__ src, const int* __restrict__ dst) {
    int e = blockIdx.x * blockDim.x + threadIdx.x;
    if (e < N_EDGES) {
        atomicAdd(&g_deg_out[src[e]], 1);
        atomicAdd(&g_deg_in[dst[e]], 1);
    }
}

__global__ void k_inv_sqrt() {
    int i = blockIdx.x * blockDim.x + threadIdx.x;
    if (i < N_NODES) {
        g_inv_out[i] = rsqrtf(fmaxf((float)g_deg_out[i], 1.0f));
        g_inv_in[i]  = rsqrtf(fmaxf((float)g_deg_in[i], 1.0f));
    }
}

__global__ void k_zero_agg() {
    size_t n4 = (size_t)N_NODES * DIM / 4;
    float4 z = make_float4(0.f, 0.f, 0.f, 0.f);
    for (size_t i = blockIdx.x * blockDim.x + threadIdx.x; i < n4;
         i += (size_t)gridDim.x * blockDim.x)
        ((float4*)g_agg)[i] = z;
}

// One warp per edge: gather feat[src]*inv_out[src], vector-reduce into g_agg[dst].
__global__ void k_scatter(const int* __restrict__ src, const int* __restrict__ dst,
                          const float* __restrict__ feat) {
    int warp = (blockIdx.x * blockDim.x + threadIdx.x) >> 5;
    int lane = threadIdx.x & 31;
    if (warp >= N_EDGES) return;
    int s = src[warp];
    int d = dst[warp];
    float w = g_inv_out[s];
    const float4* fr = (const float4*)(feat + (size_t)s * DIM);
    float4*       ar = (float4*)(g_agg + (size_t)d * DIM);
#pragma unroll
    for (int i = 0; i < 2; i++) {
        float4 v = fr[lane + 32 * i];
        v.x *= w; v.y *= w; v.z *= w; v.w *= w;
        asm volatile("red.global.add.v4.f32 [%0], {%1, %2, %3, %4};"
                     :: "l"(ar + lane + 32 * i),
                        "f"(v.x), "f"(v.y), "f"(v.z), "f"(v.w)
                     : "memory");
    }
}

// out[i,:] = relu( inv_in[i] * (A[i,:] @ W) + b )
// Classic SIMT sgemm: BM=128, BN=128, BK=16, 256 threads, 8x8 per thread.
#define BM 128
#define BN 128
#define BK 16

__global__ __launch_bounds__(256, 2)
void k_gemm_bias_relu(const float* __restrict__ A, const float* __restrict__ W,
                      const float* __restrict__ bias, float* __restrict__ out) {
    __shared__ float As[BK][BM];
    __shared__ float Bs[BK][BN];

    const int row0 = blockIdx.x * BM;
    const int col0 = blockIdx.y * BN;
    const int tid  = threadIdx.x;
    const int tx   = tid & 15;    // 0..15 -> 8 cols each
    const int ty   = tid >> 4;    // 0..15 -> 8 rows each

    float acc[8][8];
#pragma unroll
    for (int i = 0; i < 8; i++)
#pragma unroll
        for (int j = 0; j < 8; j++) acc[i][j] = 0.f;

    for (int k0 = 0; k0 < DIM; k0 += BK) {
        // A tile: BM x BK = 512 float4, 2 per thread, store transposed.
#pragma unroll
        for (int i = 0; i < 2; i++) {
            int idx = tid + i * 256;       // 0..511
            int r   = idx >> 2;            // tile row 0..127
            int c4  = idx & 3;             // float4 index within 16 cols
            int grow = row0 + r;
            float4 v = make_float4(0.f, 0.f, 0.f, 0.f);
            if (grow < N_NODES)
                v = ((const float4*)(A + (size_t)grow * DIM + k0))[c4];
            As[c4 * 4 + 0][r] = v.x;
            As[c4 * 4 + 1][r] = v.y;
            As[c4 * 4 + 2][r] = v.z;
            As[c4 * 4 + 3][r] = v.w;
        }
        // B tile: BK x BN = 512 float4, 2 per thread.
#pragma unroll
        for (int i = 0; i < 2; i++) {
            int idx = tid + i * 256;
            int r   = idx >> 5;            // k row 0..15
            int c4  = idx & 31;            // float4 col
            float4 v = ((const float4*)(W + (size_t)(k0 + r) * DIM + col0))[c4];
            ((float4*)&Bs[r][0])[c4] = v;
        }
        __syncthreads();

#pragma unroll
        for (int kk = 0; kk < BK; kk++) {
            float a[8], bb[8];
            *(float4*)&a[0]  = *(const float4*)&As[kk][ty * 8];
            *(float4*)&a[4]  = *(const float4*)&As[kk][ty * 8 + 4];
            *(float4*)&bb[0] = *(const float4*)&Bs[kk][tx * 8];
            *(float4*)&bb[4] = *(const float4*)&Bs[kk][tx * 8 + 4];
#pragma unroll
            for (int i = 0; i < 8; i++)
#pragma unroll
                for (int j = 0; j < 8; j++)
                    acc[i][j] = fmaf(a[i], bb[j], acc[i][j]);
        }
        __syncthreads();
    }

    // Epilogue: dst-side norm, bias, relu.
#pragma unroll
    for (int i = 0; i < 8; i++) {
        int grow = row0 + ty * 8 + i;
        if (grow >= N_NODES) continue;
        float sc = g_inv_in[grow];
#pragma unroll
        for (int j = 0; j < 8; j += 4) {
            int col = col0 + tx * 8 + j;
            float4 o;
            o.x = fmaxf(fmaf(acc[i][j + 0], sc, bias[col + 0]), 0.f);
            o.y = fmaxf(fmaf(acc[i][j + 1], sc, bias[col + 1]), 0.f);
            o.z = fmaxf(fmaf(acc[i][j + 2], sc, bias[col + 2]), 0.f);
            o.w = fmaxf(fmaf(acc[i][j + 3], sc, bias[col + 3]), 0.f);
            *(float4*)(out + (size_t)grow * DIM + col) = o;
        }
    }
}

// ---------------- launch ----------------

extern "C" void kernel_launch(void* const* d_in, const int* in_sizes, int n_in,
                              void* d_out, int out_size) {
    const int*   src  = (const int*)d_in[0];
    const int*   dst  = (const int*)d_in[1];
    const float* feat = (const float*)d_in[2];
    const float* W1   = (const float*)d_in[3];
    const float* b1   = (const float*)d_in[4];
    const float* W2   = (const float*)d_in[5];
    const float* b2   = (const float*)d_in[6];
    float*       out  = (float*)d_out;

    float* agg; cudaGetSymbolAddress((void**)&agg, g_agg);
    float* h;   cudaGetSymbolAddress((void**)&h,   g_h);

    const int T = 256;
    dim3 gemm_grid((N_NODES + BM - 1) / BM, DIM / BN);

    k_init_counts<<<(N_NODES + T - 1) / T, T>>>();
    k_count_deg<<<(N_EDGES + T - 1) / T, T>>>(src, dst);
    k_inv_sqrt<<<(N_NODES + T - 1) / T, T>>>();

    // ---- layer 1 ----
    k_zero_agg<<<148 * 8, T>>>();
    k_scatter<<<(N_EDGES * 32 + T - 1) / T, T>>>(src, dst, feat);
    k_gemm_bias_relu<<<gemm_grid, T>>>(agg, W1, b1, h);

    // ---- layer 2 ----
    k_zero_agg<<<148 * 8, T>>>();
    k_scatter<<<(N_EDGES * 32 + T - 1) / T, T>>>(src, dst, h);
    k_gemm_bias_relu<<<gemm_grid, T>>>(agg, W2, b2, out);
}

// round 3
// speedup vs baseline: 1.7439x; 1.7439x over previous
#include <cuda_runtime.h>
#include <cuda_bf16.h>
#include <cstdint>

#define N_NODES 100000
#define N_EDGES 320000
#define DIM 256

// ---------------- scratch (no allocations allowed) ----------------
__device__ int   g_deg_out[N_NODES];
__device__ int   g_deg_in[N_NODES];
__device__ float g_inv_out[N_NODES];
__device__ float g_inv_in[N_NODES];
__device__ float g_agg[(size_t)N_NODES * DIM];
__device__ float g_h[(size_t)N_NODES * DIM];
// A split into bf16 hi/lo (per layer, reused)
__device__ __nv_bfloat16 g_a_hi[(size_t)N_NODES * DIM];
__device__ __nv_bfloat16 g_a_lo[(size_t)N_NODES * DIM];
// W transposed to [N,K] and split into bf16 hi/lo (per layer)
__device__ __nv_bfloat16 g_bt1_hi[DIM * DIM];
__device__ __nv_bfloat16 g_bt1_lo[DIM * DIM];
__device__ __nv_bfloat16 g_bt2_hi[DIM * DIM];
__device__ __nv_bfloat16 g_bt2_lo[DIM * DIM];

// ---------------- helpers ----------------
__device__ __forceinline__ uint32_t smem_u32(const void* p) {
    uint32_t a;
    asm("{ .reg .u64 t; cvta.to.shared.u64 t, %1; cvt.u32.u64 %0, t; }" : "=r"(a) : "l"(p));
    return a;
}
__device__ __forceinline__ void cp16(uint32_t dst, const void* src, uint32_t sz) {
    asm volatile("cp.async.cg.shared.global [%0], [%1], 16, %2;"
                 :: "r"(dst), "l"(src), "r"(sz) : "memory");
}
__device__ __forceinline__ void cp_commit() {
    asm volatile("cp.async.commit_group;" ::: "memory");
}
__device__ __forceinline__ void cp_wait0() {
    asm volatile("cp.async.wait_group 0;" ::: "memory");
}
__device__ __forceinline__ void ldm4(uint32_t* r, uint32_t addr) {
    asm volatile("ldmatrix.sync.aligned.m8n8.x4.shared.b16 {%0,%1,%2,%3}, [%4];"
                 : "=r"(r[0]), "=r"(r[1]), "=r"(r[2]), "=r"(r[3]) : "r"(addr));
}
__device__ __forceinline__ void mma16816(float* c, const uint32_t* a, uint32_t b0, uint32_t b1) {
    asm volatile("mma.sync.aligned.m16n8k16.row.col.f32.bf16.bf16.f32 "
                 "{%0,%1,%2,%3}, {%4,%5,%6,%7}, {%8,%9}, {%0,%1,%2,%3};"
                 : "+f"(c[0]), "+f"(c[1]), "+f"(c[2]), "+f"(c[3])
                 : "r"(a[0]), "r"(a[1]), "r"(a[2]), "r"(a[3]), "r"(b0), "r"(b1));
}

// ---------------- graph kernels ----------------
__global__ void k_init_counts() {
    int i = blockIdx.x * blockDim.x + threadIdx.x;
    if (i < N_NODES) { g_deg_out[i] = 0; g_deg_in[i] = 0; }
}
__global__ void k_count_deg(const int* __restrict__ src, const int* __restrict__ dst) {
    int e = blockIdx.x * blockDim.x + threadIdx.x;
    if (e < N_EDGES) {
        atomicAdd(&g_deg_out[src[e]], 1);
        atomicAdd(&g_deg_in[dst[e]], 1);
    }
}
__global__ void k_inv_sqrt() {
    int i = blockIdx.x * blockDim.x + threadIdx.x;
    if (i < N_NODES) {
        g_inv_out[i] = rsqrtf(fmaxf((float)g_deg_out[i], 1.0f));
        g_inv_in[i]  = rsqrtf(fmaxf((float)g_deg_in[i], 1.0f));
    }
}
__global__ void k_zero_agg() {
    size_t n4 = (size_t)N_NODES * DIM / 4;
    float4 z = make_float4(0.f, 0.f, 0.f, 0.f);
    for (size_t i = blockIdx.x * blockDim.x + threadIdx.x; i < n4;
         i += (size_t)gridDim.x * blockDim.x)
        ((float4*)g_agg)[i] = z;
}
__global__ void k_scatter(const int* __restrict__ src, const int* __restrict__ dst,
                          const float* __restrict__ feat) {
    int warp = (blockIdx.x * blockDim.x + threadIdx.x) >> 5;
    int lane = threadIdx.x & 31;
    if (warp >= N_EDGES) return;
    int s = src[warp];
    int d = dst[warp];
    float w = g_inv_out[s];
    const float4* fr = (const float4*)(feat + (size_t)s * DIM);
    float4*       ar = (float4*)(g_agg + (size_t)d * DIM);
#pragma unroll
    for (int i = 0; i < 2; i++) {
        float4 v = fr[lane + 32 * i];
        v.x *= w; v.y *= w; v.z *= w; v.w *= w;
        asm volatile("red.global.add.v4.f32 [%0], {%1, %2, %3, %4};"
                     :: "l"(ar + lane + 32 * i),
                        "f"(v.x), "f"(v.y), "f"(v.z), "f"(v.w)
                     : "memory");
    }
}
// W [K,N] fp32 -> Bt [N,K] bf16 hi/lo
__global__ void k_prep_w(const float* __restrict__ W, __nv_bfloat16* __restrict__ bhi,
                         __nv_bfloat16* __restrict__ blo) {
    int i = blockIdx.x * blockDim.x + threadIdx.x;
    if (i >= DIM * DIM) return;
    int n = i >> 8, k = i & 255;
    float v = W[k * DIM + n];
    __nv_bfloat16 h = __float2bfloat16(v);
    bhi[i] = h;
    blo[i] = __float2bfloat16(v - __bfloat162float(h));
}
// fp32 A -> bf16 hi/lo (8 elems per thread)
__global__ void k_split_a(const float* __restrict__ a) {
    size_t i = (size_t)blockIdx.x * blockDim.x + threadIdx.x;
    size_t n8 = (size_t)N_NODES * DIM / 8;
    if (i >= n8) return;
    float4 v0 = ((const float4*)a)[2 * i];
    float4 v1 = ((const float4*)a)[2 * i + 1];
    float f[8] = {v0.x, v0.y, v0.z, v0.w, v1.x, v1.y, v1.z, v1.w};
    uint32_t ph[4], pl[4];
#pragma unroll
    for (int j = 0; j < 4; j++) {
        __nv_bfloat16 h0 = __float2bfloat16(f[2 * j]);
        __nv_bfloat16 h1 = __float2bfloat16(f[2 * j + 1]);
        __nv_bfloat16 l0 = __float2bfloat16(f[2 * j]     - __bfloat162float(h0));
        __nv_bfloat16 l1 = __float2bfloat16(f[2 * j + 1] - __bfloat162float(h1));
        ph[j] = (uint32_t)__bfloat16_as_ushort(h0) | ((uint32_t)__bfloat16_as_ushort(h1) << 16);
        pl[j] = (uint32_t)__bfloat16_as_ushort(l0) | ((uint32_t)__bfloat16_as_ushort(l1) << 16);
    }
    ((uint4*)g_a_hi)[i] = make_uint4(ph[0], ph[1], ph[2], ph[3]);
    ((uint4*)g_a_lo)[i] = make_uint4(pl[0], pl[1], pl[2], pl[3]);
}

// ---------------- HMMA GEMM: out = relu(inv_in[i]*(A@W) + b) ----------------
// BM=128, BN=128, BK=64, 2-stage cp.async. 8 warps (2m x 4n), warp tile 64x32.
// SMEM stage: [Ah 16K][Al 16K][Bh 16K][Bl 16K] = 64KB, x2 = 128KB.
#define TILE_B 16384
#define STAGE_B 65536

__global__ __launch_bounds__(256, 1)
void k_gemm_mma(const __nv_bfloat16* __restrict__ Bh_g,
                const __nv_bfloat16* __restrict__ Bl_g,
                const float* __restrict__ bias, float* __restrict__ out) {
    extern __shared__ char smem[];
    const uint32_t sb = smem_u32(smem);
    const int tid = threadIdx.x, lane = tid & 31, wid = tid >> 5;
    const int wm = wid >> 2, wn = wid & 3;
    const int row0 = blockIdx.x * 128, col0 = blockIdx.y * 128;

    float acc[4][4][4];
#pragma unroll
    for (int i = 0; i < 4; i++)
#pragma unroll
        for (int j = 0; j < 4; j++)
#pragma unroll
            for (int k = 0; k < 4; k++) acc[i][j][k] = 0.f;

    // prefetch lambda-ish macro: chunk c -> stage s
    const int pr = tid >> 3;             // 0..31 base row step handled in loop
    const int pc = tid & 7;              // 16B chunk within 64-col row
#define PREFETCH(s, c)                                                              \
    {                                                                               \
        _Pragma("unroll")                                                           \
        for (int it = 0; it < 4; it++) {                                            \
            int r = pr + it * 32;                                                   \
            uint32_t dst = sb + (s) * STAGE_B + r * 128 + ((pc ^ (r & 7)) << 4);    \
            int arow = row0 + r;                                                    \
            uint32_t ok = (arow < N_NODES) ? 16u : 0u;                              \
            if (arow >= N_NODES) arow = N_NODES - 1;                                \
            size_t aoff = (size_t)arow * DIM + (c) * 64 + pc * 8;                   \
            cp16(dst,              g_a_hi + aoff, ok);                              \
            cp16(dst + TILE_B,     g_a_lo + aoff, ok);                              \
            size_t boff = (size_t)(col0 + r) * DIM + (c) * 64 + pc * 8;             \
            cp16(dst + 2 * TILE_B, Bh_g + boff, 16u);                               \
            cp16(dst + 3 * TILE_B, Bl_g + boff, 16u);                               \
        }                                                                           \
        cp_commit();                                                                \
    }

    PREFETCH(0, 0);

#pragma unroll
    for (int c = 0; c < 4; c++) {
        cp_wait0();
        __syncthreads();
        if (c < 3) PREFETCH((c + 1) & 1, c + 1);

        const uint32_t st = sb + (c & 1) * STAGE_B;
#pragma unroll
        for (int k16 = 0; k16 < 4; k16++) {
            uint32_t ah[4][4], al[4][4];
#pragma unroll
            for (int fm = 0; fm < 4; fm++) {
                int row = wm * 64 + fm * 16 + (lane & 15);
                int kc = k16 * 2 + (lane >> 4);
                uint32_t a = st + row * 128 + ((kc ^ (row & 7)) << 4);
                ldm4(ah[fm], a);
                ldm4(al[fm], a + TILE_B);
            }
            uint32_t bh[2][4], bl[2][4];
#pragma unroll
            for (int rg = 0; rg < 2; rg++) {
                int nrow = wn * 32 + rg * 16 + (lane & 7) + ((lane & 16) >> 1);
                int kc = k16 * 2 + ((lane >> 3) & 1);
                uint32_t a = st + 2 * TILE_B + nrow * 128 + ((kc ^ (nrow & 7)) << 4);
                ldm4(bh[rg], a);
                ldm4(bl[rg], a + TILE_B);
            }
#pragma unroll
            for (int fm = 0; fm < 4; fm++)
#pragma unroll
                for (int fn = 0; fn < 4; fn++) {
                    int rg = fn >> 1, o = (fn & 1) * 2;
                    mma16816(acc[fm][fn], ah[fm], bh[rg][o], bh[rg][o + 1]);
                    mma16816(acc[fm][fn], ah[fm], bl[rg][o], bl[rg][o + 1]);
                    mma16816(acc[fm][fn], al[fm], bh[rg][o], bh[rg][o + 1]);
                }
        }
        __syncthreads();
    }

    // epilogue: dst-norm + bias + relu
#pragma unroll
    for (int fm = 0; fm < 4; fm++) {
        int mbase = row0 + wm * 64 + fm * 16 + (lane >> 2);
#pragma unroll
        for (int half = 0; half < 2; half++) {
            int row = mbase + half * 8;
            if (row >= N_NODES) continue;
            float sc = g_inv_in[row];
#pragma unroll
            for (int fn = 0; fn < 4; fn++) {
                int col = col0 + wn * 32 + fn * 8 + 2 * (lane & 3);
                float v0 = acc[fm][fn][half * 2 + 0];
                float v1 = acc[fm][fn][half * 2 + 1];
                float2 o;
                o.x = fmaxf(fmaf(v0, sc, bias[col]), 0.f);
                o.y = fmaxf(fmaf(v1, sc, bias[col + 1]), 0.f);
                *(float2*)(out + (size_t)row * DIM + col) = o;
            }
        }
    }
}

// ---------------- launch ----------------
extern "C" void kernel_launch(void* const* d_in, const int* in_sizes, int n_in,
                              void* d_out, int out_size) {
    const int*   src  = (const int*)d_in[0];
    const int*   dst  = (const int*)d_in[1];
    const float* feat = (const float*)d_in[2];
    const float* W1   = (const float*)d_in[3];
    const float* b1   = (const float*)d_in[4];
    const float* W2   = (const float*)d_in[5];
    const float* b2   = (const float*)d_in[6];
    float*       out  = (float*)d_out;

    float* agg; cudaGetSymbolAddress((void**)&agg, g_agg);
    float* h;   cudaGetSymbolAddress((void**)&h,   g_h);
    __nv_bfloat16 *bt1h, *bt1l, *bt2h, *bt2l;
    cudaGetSymbolAddress((void**)&bt1h, g_bt1_hi);
    cudaGetSymbolAddress((void**)&bt1l, g_bt1_lo);
    cudaGetSymbolAddress((void**)&bt2h, g_bt2_hi);
    cudaGetSymbolAddress((void**)&bt2l, g_bt2_lo);

    static int smem_set = 0;
    if (!smem_set) {
        cudaFuncSetAttribute(k_gemm_mma, cudaFuncAttributeMaxDynamicSharedMemorySize,
                             2 * STAGE_B);
        smem_set = 1;
    }

    const int T = 256;
    dim3 gemm_grid((N_NODES + 127) / 128, 2);
    const int split_grid = (int)(((size_t)N_NODES * DIM / 8 + T - 1) / T);

    k_init_counts<<<(N_NODES + T - 1) / T, T>>>();
    k_count_deg<<<(N_EDGES + T - 1) / T, T>>>(src, dst);
    k_inv_sqrt<<<(N_NODES + T - 1) / T, T>>>();
    k_prep_w<<<(DIM * DIM + T - 1) / T, T>>>(W1, bt1h, bt1l);
    k_prep_w<<<(DIM * DIM + T - 1) / T, T>>>(W2, bt2h, bt2l);

    // ---- layer 1 ----
    k_zero_agg<<<148 * 8, T>>>();
    k_scatter<<<(N_EDGES * 32 + T - 1) / T, T>>>(src, dst, feat);
    k_split_a<<<split_grid, T>>>(agg);
    k_gemm_mma<<<gemm_grid, T, 2 * STAGE_B>>>(bt1h, bt1l, b1, h);

    // ---- layer 2 ----
    k_zero_agg<<<148 * 8, T>>>();
    k_scatter<<<(N_EDGES * 32 + T - 1) / T, T>>>(src, dst, h);
    k_split_a<<<split_grid, T>>>(agg);
    k_gemm_mma<<<gemm_grid, T, 2 * STAGE_B>>>(bt2h, bt2l, b2, out);
}

// round 4
// speedup vs baseline: 1.7735x; 1.0170x over previous
#include <cuda_runtime.h>
#include <cuda_bf16.h>
#include <cstdint>

#define N_NODES 100000
#define N_EDGES 320000
#define DIM 256

// ---------------- scratch (no allocations allowed) ----------------
__device__ int   g_deg_out[N_NODES];
__device__ int   g_deg_in[N_NODES];
__device__ float g_inv_out[N_NODES];
__device__ float g_inv_in[N_NODES];
__device__ float g_agg[(size_t)N_NODES * DIM];
__device__ float g_h[(size_t)N_NODES * DIM];
// W transposed to [N,K] and split into bf16 hi/lo (per layer)
__device__ __nv_bfloat16 g_bt1_hi[DIM * DIM];
__device__ __nv_bfloat16 g_bt1_lo[DIM * DIM];
__device__ __nv_bfloat16 g_bt2_hi[DIM * DIM];
__device__ __nv_bfloat16 g_bt2_lo[DIM * DIM];

// ---------------- helpers ----------------
__device__ __forceinline__ uint32_t smem_u32(const void* p) {
    uint32_t a;
    asm("{ .reg .u64 t; cvta.to.shared.u64 t, %1; cvt.u32.u64 %0, t; }" : "=r"(a) : "l"(p));
    return a;
}
__device__ __forceinline__ void cp16(uint32_t dst, const void* src) {
    asm volatile("cp.async.cg.shared.global [%0], [%1], 16;"
                 :: "r"(dst), "l"(src) : "memory");
}
__device__ __forceinline__ void cp_commit() {
    asm volatile("cp.async.commit_group;" ::: "memory");
}
__device__ __forceinline__ void cp_wait0() {
    asm volatile("cp.async.wait_group 0;" ::: "memory");
}
__device__ __forceinline__ void ldm4(uint32_t* r, uint32_t addr) {
    asm volatile("ldmatrix.sync.aligned.m8n8.x4.shared.b16 {%0,%1,%2,%3}, [%4];"
                 : "=r"(r[0]), "=r"(r[1]), "=r"(r[2]), "=r"(r[3]) : "r"(addr));
}
__device__ __forceinline__ void mma16816(float* c, const uint32_t* a, uint32_t b0, uint32_t b1) {
    asm volatile("mma.sync.aligned.m16n8k16.row.col.f32.bf16.bf16.f32 "
                 "{%0,%1,%2,%3}, {%4,%5,%6,%7}, {%8,%9}, {%0,%1,%2,%3};"
                 : "+f"(c[0]), "+f"(c[1]), "+f"(c[2]), "+f"(c[3])
                 : "r"(a[0]), "r"(a[1]), "r"(a[2]), "r"(a[3]), "r"(b0), "r"(b1));
}
#define SWZ(x) ((x) ^ (((x) >> 3) & 0x70))

// ---------------- graph kernels ----------------
__global__ void k_init_counts() {
    int i = blockIdx.x * blockDim.x + threadIdx.x;
    if (i < N_NODES) { g_deg_out[i] = 0; g_deg_in[i] = 0; }
}
__global__ void k_count_deg(const int* __restrict__ src, const int* __restrict__ dst) {
    int e = blockIdx.x * blockDim.x + threadIdx.x;
    if (e < N_EDGES) {
        atomicAdd(&g_deg_out[src[e]], 1);
        atomicAdd(&g_deg_in[dst[e]], 1);
    }
}
__global__ void k_inv_sqrt() {
    int i = blockIdx.x * blockDim.x + threadIdx.x;
    if (i < N_NODES) {
        g_inv_out[i] = rsqrtf(fmaxf((float)g_deg_out[i], 1.0f));
        g_inv_in[i]  = rsqrtf(fmaxf((float)g_deg_in[i], 1.0f));
    }
}
__global__ void k_zero_agg() {
    size_t n4 = (size_t)N_NODES * DIM / 4;
    float4 z = make_float4(0.f, 0.f, 0.f, 0.f);
    for (size_t i = blockIdx.x * blockDim.x + threadIdx.x; i < n4;
         i += (size_t)gridDim.x * blockDim.x)
        ((float4*)g_agg)[i] = z;
}
__global__ void k_scatter(const int* __restrict__ src, const int* __restrict__ dst,
                          const float* __restrict__ feat) {
    int warp = (blockIdx.x * blockDim.x + threadIdx.x) >> 5;
    int lane = threadIdx.x & 31;
    if (warp >= N_EDGES) return;
    int s = src[warp];
    int d = dst[warp];
    float w = g_inv_out[s];
    const float4* fr = (const float4*)(feat + (size_t)s * DIM);
    float4*       ar = (float4*)(g_agg + (size_t)d * DIM);
#pragma unroll
    for (int i = 0; i < 2; i++) {
        float4 v = fr[lane + 32 * i];
        v.x *= w; v.y *= w; v.z *= w; v.w *= w;
        asm volatile("red.global.add.v4.f32 [%0], {%1, %2, %3, %4};"
                     :: "l"(ar + lane + 32 * i),
                        "f"(v.x), "f"(v.y), "f"(v.z), "f"(v.w)
                     : "memory");
    }
}
// W [K,N] fp32 -> Bt [N,K] bf16 hi/lo
__global__ void k_prep_w(const float* __restrict__ W, __nv_bfloat16* __restrict__ bhi,
                         __nv_bfloat16* __restrict__ blo) {
    int i = blockIdx.x * blockDim.x + threadIdx.x;
    if (i >= DIM * DIM) return;
    int n = i >> 8, k = i & 255;
    float v = W[k * DIM + n];
    __nv_bfloat16 h = __float2bfloat16(v);
    bhi[i] = h;
    blo[i] = __float2bfloat16(v - __bfloat162float(h));
}

// ---------------- HMMA GEMM: out = relu(inv_in[i]*(A@W) + b) ----------------
// BM=128, BN=128, BK=64. A loaded fp32 via LDG, split to bf16 hi/lo in-regs,
// STS'd swizzled. B hi/lo via cp.async. 8 warps (2m x 4n), warp tile 64x32.
// Stage: [Ah 16K][Al 16K][Bh 16K][Bl 16K] = 64KB x2 = 128KB.
#define TILE_B 16384
#define STAGE_B 65536

__global__ __launch_bounds__(256, 1)
void k_gemm_mma(const float* __restrict__ A,
                const __nv_bfloat16* __restrict__ Bh_g,
                const __nv_bfloat16* __restrict__ Bl_g,
                const float* __restrict__ bias, float* __restrict__ out) {
    extern __shared__ char smem[];
    const uint32_t sb = smem_u32(smem);
    const int tid = threadIdx.x, lane = tid & 31, wid = tid >> 5;
    const int wm = wid >> 2, wn = wid & 3;
    const int row0 = (blockIdx.x >> 1) * 128, col0 = (blockIdx.x & 1) * 128;

    float acc[4][4][4];
#pragma unroll
    for (int i = 0; i < 4; i++)
#pragma unroll
        for (int j = 0; j < 4; j++)
#pragma unroll
            for (int k = 0; k < 4; k++) acc[i][j][k] = 0.f;

    const int pr = tid >> 3;   // A unit row base / B row base
    const int pc = tid & 7;    // 16B chunk (8 elems) within 64-col chunk

    // A fp32 prefetch registers: 4 units x 8 floats
    float4 rA[4][2];

#define LDGA(c)                                                                     \
    {                                                                               \
        _Pragma("unroll")                                                           \
        for (int it = 0; it < 4; it++) {                                            \
            int id = tid + it * 256;                                                \
            int r = id >> 3, c8 = id & 7;                                           \
            int arow = row0 + r;                                                    \
            if (arow < N_NODES) {                                                   \
                const float4* p = (const float4*)(A + (size_t)arow * DIM + (c) * 64 + c8 * 8); \
                rA[it][0] = p[0]; rA[it][1] = p[1];                                 \
            } else {                                                                \
                rA[it][0] = make_float4(0.f, 0.f, 0.f, 0.f);                        \
                rA[it][1] = rA[it][0];                                              \
            }                                                                       \
        }                                                                           \
    }
#define CPB(s, c)                                                                   \
    {                                                                               \
        _Pragma("unroll")                                                           \
        for (int it = 0; it < 4; it++) {                                            \
            int r = pr + it * 32;                                                   \
            uint32_t dst = sb + (s) * STAGE_B + 2 * TILE_B + r * 128 + ((pc ^ (r & 7)) << 4); \
            size_t boff = (size_t)(col0 + r) * DIM + (c) * 64 + pc * 8;             \
            cp16(dst, Bh_g + boff);                                                 \
            cp16(dst + TILE_B, Bl_g + boff);                                        \
        }                                                                           \
        cp_commit();                                                                \
    }

    LDGA(0);
    CPB(0, 0);

#pragma unroll
    for (int c = 0; c < 4; c++) {
        const int s = c & 1;
        const uint32_t st = sb + s * STAGE_B;
        cp_wait0();

        // convert + STS A hi/lo into stage s
#pragma unroll
        for (int it = 0; it < 4; it++) {
            int id = tid + it * 256;
            int r = id >> 3, c8 = id & 7;
            float f[8] = {rA[it][0].x, rA[it][0].y, rA[it][0].z, rA[it][0].w,
                          rA[it][1].x, rA[it][1].y, rA[it][1].z, rA[it][1].w};
            uint32_t ph[4], pl[4];
#pragma unroll
            for (int j = 0; j < 4; j++) {
                __nv_bfloat16 h0 = __float2bfloat16(f[2 * j]);
                __nv_bfloat16 h1 = __float2bfloat16(f[2 * j + 1]);
                __nv_bfloat16 l0 = __float2bfloat16(f[2 * j]     - __bfloat162float(h0));
                __nv_bfloat16 l1 = __float2bfloat16(f[2 * j + 1] - __bfloat162float(h1));
                ph[j] = (uint32_t)__bfloat16_as_ushort(h0) | ((uint32_t)__bfloat16_as_ushort(h1) << 16);
                pl[j] = (uint32_t)__bfloat16_as_ushort(l0) | ((uint32_t)__bfloat16_as_ushort(l1) << 16);
            }
            uint32_t so = SWZ((uint32_t)(r * 128 + c8 * 16));
            *(uint4*)(smem + s * STAGE_B + so)          = make_uint4(ph[0], ph[1], ph[2], ph[3]);
            *(uint4*)(smem + s * STAGE_B + TILE_B + so) = make_uint4(pl[0], pl[1], pl[2], pl[3]);
        }
        __syncthreads();

        if (c < 3) { LDGA(c + 1); CPB(1 - s, c + 1); }

#pragma unroll
        for (int k16 = 0; k16 < 4; k16++) {
            uint32_t ah[4][4], al[4][4];
#pragma unroll
            for (int fm = 0; fm < 4; fm++) {
                int row = wm * 64 + fm * 16 + (lane & 15);
                int kc = k16 * 2 + (lane >> 4);
                uint32_t a = st + row * 128 + ((kc ^ (row & 7)) << 4);
                ldm4(ah[fm], a);
                ldm4(al[fm], a + TILE_B);
            }
            uint32_t bh[2][4], bl[2][4];
#pragma unroll
            for (int rg = 0; rg < 2; rg++) {
                int nrow = wn * 32 + rg * 16 + (lane & 7) + ((lane & 16) >> 1);
                int kc = k16 * 2 + ((lane >> 3) & 1);
                uint32_t a = st + 2 * TILE_B + nrow * 128 + ((kc ^ (nrow & 7)) << 4);
                ldm4(bh[rg], a);
                ldm4(bl[rg], a + TILE_B);
            }
#pragma unroll
            for (int fm = 0; fm < 4; fm++)
#pragma unroll
                for (int fn = 0; fn < 4; fn++) {
                    int rg = fn >> 1, o = (fn & 1) * 2;
                    mma16816(acc[fm][fn], ah[fm], bh[rg][o], bh[rg][o + 1]);
                    mma16816(acc[fm][fn], ah[fm], bl[rg][o], bl[rg][o + 1]);
                    mma16816(acc[fm][fn], al[fm], bh[rg][o], bh[rg][o + 1]);
                }
        }
        __syncthreads();
    }

    // epilogue: dst-norm + bias + relu
#pragma unroll
    for (int fm = 0; fm < 4; fm++) {
        int mbase = row0 + wm * 64 + fm * 16 + (lane >> 2);
#pragma unroll
        for (int half = 0; half < 2; half++) {
            int row = mbase + half * 8;
            if (row >= N_NODES) continue;
            float sc = g_inv_in[row];
#pragma unroll
            for (int fn = 0; fn < 4; fn++) {
                int col = col0 + wn * 32 + fn * 8 + 2 * (lane & 3);
                float v0 = acc[fm][fn][half * 2 + 0];
                float v1 = acc[fm][fn][half * 2 + 1];
                float2 o;
                o.x = fmaxf(fmaf(v0, sc, bias[col]), 0.f);
                o.y = fmaxf(fmaf(v1, sc, bias[col + 1]), 0.f);
                *(float2*)(out + (size_t)row * DIM + col) = o;
            }
        }
    }
}

// ---------------- launch ----------------
extern "C" void kernel_launch(void* const* d_in, const int* in_sizes, int n_in,
                              void* d_out, int out_size) {
    const int*   src  = (const int*)d_in[0];
    const int*   dst  = (const int*)d_in[1];
    const float* feat = (const float*)d_in[2];
    const float* W1   = (const float*)d_in[3];
    const float* b1   = (const float*)d_in[4];
    const float* W2   = (const float*)d_in[5];
    const float* b2   = (const float*)d_in[6];
    float*       out  = (float*)d_out;

    float* agg; cudaGetSymbolAddress((void**)&agg, g_agg);
    float* h;   cudaGetSymbolAddress((void**)&h,   g_h);
    __nv_bfloat16 *bt1h, *bt1l, *bt2h, *bt2l;
    cudaGetSymbolAddress((void**)&bt1h, g_bt1_hi);
    cudaGetSymbolAddress((void**)&bt1l, g_bt1_lo);
    cudaGetSymbolAddress((void**)&bt2h, g_bt2_hi);
    cudaGetSymbolAddress((void**)&bt2l, g_bt2_lo);

    static int smem_set = 0;
    if (!smem_set) {
        cudaFuncSetAttribute(k_gemm_mma, cudaFuncAttributeMaxDynamicSharedMemorySize,
                             2 * STAGE_B);
        smem_set = 1;
    }

    const int T = 256;
    const int gemm_grid = ((N_NODES + 127) / 128) * 2;

    k_init_counts<<<(N_NODES + T - 1) / T, T>>>();
    k_count_deg<<<(N_EDGES + T - 1) / T, T>>>(src, dst);
    k_inv_sqrt<<<(N_NODES + T - 1) / T, T>>>();
    k_prep_w<<<(DIM * DIM + T - 1) / T, T>>>(W1, bt1h, bt1l);
    k_prep_w<<<(DIM * DIM + T - 1) / T, T>>>(W2, bt2h, bt2l);

    // ---- layer 1 ----
    k_zero_agg<<<148 * 8, T>>>();
    k_scatter<<<(N_EDGES * 32 + T - 1) / T, T>>>(src, dst, feat);
    k_gemm_mma<<<gemm_grid, T, 2 * STAGE_B>>>(agg, bt1h, bt1l, b1, h);

    // ---- layer 2 ----
    k_zero_agg<<<148 * 8, T>>>();
    k_scatter<<<(N_EDGES * 32 + T - 1) / T, T>>>(src, dst, h);
    k_gemm_mma<<<gemm_grid, T, 2 * STAGE_B>>>(agg, bt2h, bt2l, b2, out);
}

// round 5
// speedup vs baseline: 2.1182x; 1.1943x over previous
#include <cuda_runtime.h>
#include <cuda_bf16.h>
#include <cstdint>

#define N_NODES 100000
#define N_EDGES 320000
#define DIM 256

#define SCAN_B 256
#define NBLK ((N_NODES + SCAN_B - 1) / SCAN_B)

// ---------------- scratch (no allocations allowed) ----------------
__device__ int   g_deg_out[N_NODES];
__device__ int   g_deg_in[N_NODES];
__device__ float g_inv_out[N_NODES];
__device__ float g_inv_in[N_NODES];
__device__ float g_agg[(size_t)N_NODES * DIM];
__device__ float g_h[(size_t)N_NODES * DIM];
// CSR (by dst)
__device__ int g_off[N_NODES + 1];
__device__ int g_cur[N_NODES];
__device__ int g_part[NBLK];
__device__ int g_esrc[N_EDGES];
// W transposed to [N,K] and split into bf16 hi/lo (per layer)
__device__ __nv_bfloat16 g_bt1_hi[DIM * DIM];
__device__ __nv_bfloat16 g_bt1_lo[DIM * DIM];
__device__ __nv_bfloat16 g_bt2_hi[DIM * DIM];
__device__ __nv_bfloat16 g_bt2_lo[DIM * DIM];

// ---------------- helpers ----------------
__device__ __forceinline__ uint32_t smem_u32(const void* p) {
    uint32_t a;
    asm("{ .reg .u64 t; cvta.to.shared.u64 t, %1; cvt.u32.u64 %0, t; }" : "=r"(a) : "l"(p));
    return a;
}
__device__ __forceinline__ void cp16(uint32_t dst, const void* src) {
    asm volatile("cp.async.cg.shared.global [%0], [%1], 16;"
                 :: "r"(dst), "l"(src) : "memory");
}
__device__ __forceinline__ void cp_commit() {
    asm volatile("cp.async.commit_group;" ::: "memory");
}
__device__ __forceinline__ void cp_wait0() {
    asm volatile("cp.async.wait_group 0;" ::: "memory");
}
__device__ __forceinline__ void ldm4(uint32_t* r, uint32_t addr) {
    asm volatile("ldmatrix.sync.aligned.m8n8.x4.shared.b16 {%0,%1,%2,%3}, [%4];"
                 : "=r"(r[0]), "=r"(r[1]), "=r"(r[2]), "=r"(r[3]) : "r"(addr));
}
__device__ __forceinline__ void mma16816(float* c, const uint32_t* a, uint32_t b0, uint32_t b1) {
    asm volatile("mma.sync.aligned.m16n8k16.row.col.f32.bf16.bf16.f32 "
                 "{%0,%1,%2,%3}, {%4,%5,%6,%7}, {%8,%9}, {%0,%1,%2,%3};"
                 : "+f"(c[0]), "+f"(c[1]), "+f"(c[2]), "+f"(c[3])
                 : "r"(a[0]), "r"(a[1]), "r"(a[2]), "r"(a[3]), "r"(b0), "r"(b1));
}
#define SWZ(x) ((x) ^ (((x) >> 3) & 0x70))

// ---------------- graph prep kernels ----------------
__global__ void k_init_counts() {
    int i = blockIdx.x * blockDim.x + threadIdx.x;
    if (i < N_NODES) { g_deg_out[i] = 0; g_deg_in[i] = 0; }
}
__global__ void k_count_deg(const int* __restrict__ src, const int* __restrict__ dst) {
    int e = blockIdx.x * blockDim.x + threadIdx.x;
    if (e < N_EDGES) {
        atomicAdd(&g_deg_out[src[e]], 1);
        atomicAdd(&g_deg_in[dst[e]], 1);
    }
}
__global__ void k_inv_sqrt() {
    int i = blockIdx.x * blockDim.x + threadIdx.x;
    if (i < N_NODES) {
        g_inv_out[i] = rsqrtf(fmaxf((float)g_deg_out[i], 1.0f));
        g_inv_in[i]  = rsqrtf(fmaxf((float)g_deg_in[i], 1.0f));
    }
}
// 3-kernel exclusive scan of g_deg_in -> g_off, init g_cur
__global__ void k_scan1() {
    __shared__ int sh[SCAN_B];
    int i = blockIdx.x * SCAN_B + threadIdx.x;
    int v = (i < N_NODES) ? g_deg_in[i] : 0;
    sh[threadIdx.x] = v;
    __syncthreads();
#pragma unroll
    for (int o = 1; o < SCAN_B; o <<= 1) {
        int t = (threadIdx.x >= o) ? sh[threadIdx.x - o] : 0;
        __syncthreads();
        sh[threadIdx.x] += t;
        __syncthreads();
    }
    if (i < N_NODES) g_off[i] = sh[threadIdx.x] - v;
    if (threadIdx.x == SCAN_B - 1) g_part[blockIdx.x] = sh[SCAN_B - 1];
}
__global__ void k_scan2() {
    __shared__ int sh[512];
    int t = threadIdx.x;
    int v = (t < NBLK) ? g_part[t] : 0;
    sh[t] = v;
    __syncthreads();
#pragma unroll
    for (int o = 1; o < 512; o <<= 1) {
        int x = (t >= o) ? sh[t - o] : 0;
        __syncthreads();
        sh[t] += x;
        __syncthreads();
    }
    if (t < NBLK) g_part[t] = sh[t] - v;
}
__global__ void k_scan3() {
    int i = blockIdx.x * SCAN_B + threadIdx.x;
    if (i < N_NODES) {
        int o = g_off[i] + g_part[blockIdx.x];
        g_off[i] = o;
        g_cur[i] = o;
    }
    if (i == 0) g_off[N_NODES] = N_EDGES;
}
__global__ void k_bucket(const int* __restrict__ src, const int* __restrict__ dst) {
    int e = blockIdx.x * blockDim.x + threadIdx.x;
    if (e < N_EDGES) {
        int p = atomicAdd(&g_cur[dst[e]], 1);
        g_esrc[p] = src[e];
    }
}
// W [K,N] fp32 -> Bt [N,K] bf16 hi/lo
__global__ void k_prep_w(const float* __restrict__ W, __nv_bfloat16* __restrict__ bhi,
                         __nv_bfloat16* __restrict__ blo) {
    int i = blockIdx.x * blockDim.x + threadIdx.x;
    if (i >= DIM * DIM) return;
    int n = i >> 8, k = i & 255;
    float v = W[k * DIM + n];
    __nv_bfloat16 h = __float2bfloat16(v);
    bhi[i] = h;
    blo[i] = __float2bfloat16(v - __bfloat162float(h));
}

// ---------------- CSR gather: agg[n] = sum_{e: dst=n} inv_out[src] * feat[src] ----------------
// One warp per node; lane owns float4 slots {lane, lane+32}. 2-edge unroll for MLP.
__global__ __launch_bounds__(256)
void k_gather(const float* __restrict__ feat) {
    int node = (blockIdx.x * blockDim.x + threadIdx.x) >> 5;
    int lane = threadIdx.x & 31;
    if (node >= N_NODES) return;
    int e0 = g_off[node], e1 = g_off[node + 1];

    float4 a0 = make_float4(0.f, 0.f, 0.f, 0.f);
    float4 a1 = a0;

    int e = e0;
    for (; e + 2 <= e1; e += 2) {
        int sA = g_esrc[e], sB = g_esrc[e + 1];
        float wA = g_inv_out[sA], wB = g_inv_out[sB];
        const float4* fA = (const float4*)(feat + (size_t)sA * DIM);
        const float4* fB = (const float4*)(feat + (size_t)sB * DIM);
        float4 vA0 = fA[lane], vA1 = fA[lane + 32];
        float4 vB0 = fB[lane], vB1 = fB[lane + 32];
        a0.x = fmaf(wA, vA0.x, a0.x); a0.y = fmaf(wA, vA0.y, a0.y);
        a0.z = fmaf(wA, vA0.z, a0.z); a0.w = fmaf(wA, vA0.w, a0.w);
        a1.x = fmaf(wA, vA1.x, a1.x); a1.y = fmaf(wA, vA1.y, a1.y);
        a1.z = fmaf(wA, vA1.z, a1.z); a1.w = fmaf(wA, vA1.w, a1.w);
        a0.x = fmaf(wB, vB0.x, a0.x); a0.y = fmaf(wB, vB0.y, a0.y);
        a0.z = fmaf(wB, vB0.z, a0.z); a0.w = fmaf(wB, vB0.w, a0.w);
        a1.x = fmaf(wB, vB1.x, a1.x); a1.y = fmaf(wB, vB1.y, a1.y);
        a1.z = fmaf(wB, vB1.z, a1.z); a1.w = fmaf(wB, vB1.w, a1.w);
    }
    if (e < e1) {
        int s = g_esrc[e];
        float w = g_inv_out[s];
        const float4* fr = (const float4*)(feat + (size_t)s * DIM);
        float4 v0 = fr[lane], v1 = fr[lane + 32];
        a0.x = fmaf(w, v0.x, a0.x); a0.y = fmaf(w, v0.y, a0.y);
        a0.z = fmaf(w, v0.z, a0.z); a0.w = fmaf(w, v0.w, a0.w);
        a1.x = fmaf(w, v1.x, a1.x); a1.y = fmaf(w, v1.y, a1.y);
        a1.z = fmaf(w, v1.z, a1.z); a1.w = fmaf(w, v1.w, a1.w);
    }
    float4* ar = (float4*)(g_agg + (size_t)node * DIM);
    ar[lane]      = a0;
    ar[lane + 32] = a1;
}

// ---------------- HMMA GEMM: out = relu(inv_in[i]*(A@W) + b) ----------------
#define TILE_B 16384
#define STAGE_B 65536

__global__ __launch_bounds__(256, 1)
void k_gemm_mma(const float* __restrict__ A,
                const __nv_bfloat16* __restrict__ Bh_g,
                const __nv_bfloat16* __restrict__ Bl_g,
                const float* __restrict__ bias, float* __restrict__ out) {
    extern __shared__ char smem[];
    const uint32_t sb = smem_u32(smem);
    const int tid = threadIdx.x, lane = tid & 31, wid = tid >> 5;
    const int wm = wid >> 2, wn = wid & 3;
    const int row0 = (blockIdx.x >> 1) * 128, col0 = (blockIdx.x & 1) * 128;

    float acc[4][4][4];
#pragma unroll
    for (int i = 0; i < 4; i++)
#pragma unroll
        for (int j = 0; j < 4; j++)
#pragma unroll
            for (int k = 0; k < 4; k++) acc[i][j][k] = 0.f;

    const int pr = tid >> 3;
    const int pc = tid & 7;
    float4 rA[4][2];

#define LDGA(c)                                                                     \
    {                                                                               \
        _Pragma("unroll")                                                           \
        for (int it = 0; it < 4; it++) {                                            \
            int id = tid + it * 256;                                                \
            int r = id >> 3, c8 = id & 7;                                           \
            int arow = row0 + r;                                                    \
            if (arow < N_NODES) {                                                   \
                const float4* p = (const float4*)(A + (size_t)arow * DIM + (c) * 64 + c8 * 8); \
                rA[it][0] = p[0]; rA[it][1] = p[1];                                 \
            } else {                                                                \
                rA[it][0] = make_float4(0.f, 0.f, 0.f, 0.f);                        \
                rA[it][1] = rA[it][0];                                              \
            }                                                                       \
        }                                                                           \
    }
#define CPB(s, c)                                                                   \
    {                                                                               \
        _Pragma("unroll")                                                           \
        for (int it = 0; it < 4; it++) {                                            \
            int r = pr + it * 32;                                                   \
            uint32_t dst = sb + (s) * STAGE_B + 2 * TILE_B + r * 128 + ((pc ^ (r & 7)) << 4); \
            size_t boff = (size_t)(col0 + r) * DIM + (c) * 64 + pc * 8;             \
            cp16(dst, Bh_g + boff);                                                 \
            cp16(dst + TILE_B, Bl_g + boff);                                        \
        }                                                                           \
        cp_commit();                                                                \
    }

    LDGA(0);
    CPB(0, 0);

#pragma unroll
    for (int c = 0; c < 4; c++) {
        const int s = c & 1;
        const uint32_t st = sb + s * STAGE_B;
        cp_wait0();

#pragma unroll
        for (int it = 0; it < 4; it++) {
            int id = tid + it * 256;
            int r = id >> 3, c8 = id & 7;
            float f[8] = {rA[it][0].x, rA[it][0].y, rA[it][0].z, rA[it][0].w,
                          rA[it][1].x, rA[it][1].y, rA[it][1].z, rA[it][1].w};
            uint32_t ph[4], pl[4];
#pragma unroll
            for (int j = 0; j < 4; j++) {
                __nv_bfloat16 h0 = __float2bfloat16(f[2 * j]);
                __nv_bfloat16 h1 = __float2bfloat16(f[2 * j + 1]);
                __nv_bfloat16 l0 = __float2bfloat16(f[2 * j]     - __bfloat162float(h0));
                __nv_bfloat16 l1 = __float2bfloat16(f[2 * j + 1] - __bfloat162float(h1));
                ph[j] = (uint32_t)__bfloat16_as_ushort(h0) | ((uint32_t)__bfloat16_as_ushort(h1) << 16);
                pl[j] = (uint32_t)__bfloat16_as_ushort(l0) | ((uint32_t)__bfloat16_as_ushort(l1) << 16);
            }
            uint32_t so = SWZ((uint32_t)(r * 128 + c8 * 16));
            *(uint4*)(smem + s * STAGE_B + so)          = make_uint4(ph[0], ph[1], ph[2], ph[3]);
            *(uint4*)(smem + s * STAGE_B + TILE_B + so) = make_uint4(pl[0], pl[1], pl[2], pl[3]);
        }
        __syncthreads();

        if (c < 3) { LDGA(c + 1); CPB(1 - s, c + 1); }

#pragma unroll
        for (int k16 = 0; k16 < 4; k16++) {
            uint32_t ah[4][4], al[4][4];
#pragma unroll
            for (int fm = 0; fm < 4; fm++) {
                int row = wm * 64 + fm * 16 + (lane & 15);
                int kc = k16 * 2 + (lane >> 4);
                uint32_t a = st + row * 128 + ((kc ^ (row & 7)) << 4);
                ldm4(ah[fm], a);
                ldm4(al[fm], a + TILE_B);
            }
            uint32_t bh[2][4], bl[2][4];
#pragma unroll
            for (int rg = 0; rg < 2; rg++) {
                int nrow = wn * 32 + rg * 16 + (lane & 7) + ((lane & 16) >> 1);
                int kc = k16 * 2 + ((lane >> 3) & 1);
                uint32_t a = st + 2 * TILE_B + nrow * 128 + ((kc ^ (nrow & 7)) << 4);
                ldm4(bh[rg], a);
                ldm4(bl[rg], a + TILE_B);
            }
#pragma unroll
            for (int fm = 0; fm < 4; fm++)
#pragma unroll
                for (int fn = 0; fn < 4; fn++) {
                    int rg = fn >> 1, o = (fn & 1) * 2;
                    mma16816(acc[fm][fn], ah[fm], bh[rg][o], bh[rg][o + 1]);
                    mma16816(acc[fm][fn], ah[fm], bl[rg][o], bl[rg][o + 1]);
                    mma16816(acc[fm][fn], al[fm], bh[rg][o], bh[rg][o + 1]);
                }
        }
        __syncthreads();
    }

#pragma unroll
    for (int fm = 0; fm < 4; fm++) {
        int mbase = row0 + wm * 64 + fm * 16 + (lane >> 2);
#pragma unroll
        for (int half = 0; half < 2; half++) {
            int row = mbase + half * 8;
            if (row >= N_NODES) continue;
            float sc = g_inv_in[row];
#pragma unroll
            for (int fn = 0; fn < 4; fn++) {
                int col = col0 + wn * 32 + fn * 8 + 2 * (lane & 3);
                float v0 = acc[fm][fn][half * 2 + 0];
                float v1 = acc[fm][fn][half * 2 + 1];
                float2 o;
                o.x = fmaxf(fmaf(v0, sc, bias[col]), 0.f);
                o.y = fmaxf(fmaf(v1, sc, bias[col + 1]), 0.f);
                *(float2*)(out + (size_t)row * DIM + col) = o;
            }
        }
    }
}

// ---------------- launch ----------------
extern "C" void kernel_launch(void* const* d_in, const int* in_sizes, int n_in,
                              void* d_out, int out_size) {
    const int*   src  = (const int*)d_in[0];
    const int*   dst  = (const int*)d_in[1];
    const float* feat = (const float*)d_in[2];
    const float* W1   = (const float*)d_in[3];
    const float* b1   = (const float*)d_in[4];
    const float* W2   = (const float*)d_in[5];
    const float* b2   = (const float*)d_in[6];
    float*       out  = (float*)d_out;

    float* agg; cudaGetSymbolAddress((void**)&agg, g_agg);
    float* h;   cudaGetSymbolAddress((void**)&h,   g_h);
    __nv_bfloat16 *bt1h, *bt1l, *bt2h, *bt2l;
    cudaGetSymbolAddress((void**)&bt1h, g_bt1_hi);
    cudaGetSymbolAddress((void**)&bt1l, g_bt1_lo);
    cudaGetSymbolAddress((void**)&bt2h, g_bt2_hi);
    cudaGetSymbolAddress((void**)&bt2l, g_bt2_lo);

    static int smem_set = 0;
    if (!smem_set) {
        cudaFuncSetAttribute(k_gemm_mma, cudaFuncAttributeMaxDynamicSharedMemorySize,
                             2 * STAGE_B);
        smem_set = 1;
    }

    const int T = 256;
    const int gemm_grid = ((N_NODES + 127) / 128) * 2;
    const int gather_grid = (N_NODES * 32 + T - 1) / T;

    // ---- prep (degrees, CSR, weight split) ----
    k_init_counts<<<(N_NODES + T - 1) / T, T>>>();
    k_count_deg<<<(N_EDGES + T - 1) / T, T>>>(src, dst);
    k_inv_sqrt<<<(N_NODES + T - 1) / T, T>>>();
    k_scan1<<<NBLK, SCAN_B>>>();
    k_scan2<<<1, 512>>>();
    k_scan3<<<NBLK, SCAN_B>>>();
    k_bucket<<<(N_EDGES + T - 1) / T, T>>>(src, dst);
    k_prep_w<<<(DIM * DIM + T - 1) / T, T>>>(W1, bt1h, bt1l);
    k_prep_w<<<(DIM * DIM + T - 1) / T, T>>>(W2, bt2h, bt2l);

    // ---- layer 1 ----
    k_gather<<<gather_grid, T>>>(feat);
    k_gemm_mma<<<gemm_grid, T, 2 * STAGE_B>>>(agg, bt1h, bt1l, b1, h);

    // ---- layer 2 ----
    k_gather<<<gather_grid, T>>>(h);
    k_gemm_mma<<<gemm_grid, T, 2 * STAGE_B>>>(agg, bt2h, bt2l, b2, out);
}

// round 6
// speedup vs baseline: 2.5109x; 1.1854x over previous
#include <cuda_runtime.h>
#include <cuda_bf16.h>
#include <cstdint>

#define N_NODES 100000
#define N_EDGES 320000
#define DIM 256
#define PAD_ROWS 128

#define SCAN_B 256
#define NBLK ((N_NODES + SCAN_B - 1) / SCAN_B)

// ---------------- scratch (no allocations allowed) ----------------
__device__ int   g_deg_out[N_NODES];
__device__ int   g_deg_in[N_NODES];
__device__ float g_inv_out[N_NODES];
__device__ float g_inv_in[N_NODES];
__device__ float g_h[(size_t)N_NODES * DIM];
// gather output, pre-split bf16 (padded so full GEMM tiles read in-bounds)
__device__ __nv_bfloat16 g_a_hi[(size_t)(N_NODES + PAD_ROWS) * DIM];
__device__ __nv_bfloat16 g_a_lo[(size_t)(N_NODES + PAD_ROWS) * DIM];
// CSR (by dst)
__device__ int g_off[N_NODES + 1];
__device__ int g_cur[N_NODES];
__device__ int g_part[NBLK];
__device__ int g_esrc[N_EDGES];
// W transposed to [N,K], bf16 hi/lo
__device__ __nv_bfloat16 g_bt1_hi[DIM * DIM];
__device__ __nv_bfloat16 g_bt1_lo[DIM * DIM];
__device__ __nv_bfloat16 g_bt2_hi[DIM * DIM];
__device__ __nv_bfloat16 g_bt2_lo[DIM * DIM];

// ---------------- helpers ----------------
__device__ __forceinline__ uint32_t smem_u32(const void* p) {
    uint32_t a;
    asm("{ .reg .u64 t; cvta.to.shared.u64 t, %1; cvt.u32.u64 %0, t; }" : "=r"(a) : "l"(p));
    return a;
}
__device__ __forceinline__ void cp16(uint32_t dst, const void* src) {
    asm volatile("cp.async.cg.shared.global [%0], [%1], 16;"
                 :: "r"(dst), "l"(src) : "memory");
}
__device__ __forceinline__ void cp_commit() {
    asm volatile("cp.async.commit_group;" ::: "memory");
}
__device__ __forceinline__ void cp_wait0() {
    asm volatile("cp.async.wait_group 0;" ::: "memory");
}
__device__ __forceinline__ void ldm4(uint32_t* r, uint32_t addr) {
    asm volatile("ldmatrix.sync.aligned.m8n8.x4.shared.b16 {%0,%1,%2,%3}, [%4];"
                 : "=r"(r[0]), "=r"(r[1]), "=r"(r[2]), "=r"(r[3]) : "r"(addr));
}
__device__ __forceinline__ void mma16816(float* c, const uint32_t* a, uint32_t b0, uint32_t b1) {
    asm volatile("mma.sync.aligned.m16n8k16.row.col.f32.bf16.bf16.f32 "
                 "{%0,%1,%2,%3}, {%4,%5,%6,%7}, {%8,%9}, {%0,%1,%2,%3};"
                 : "+f"(c[0]), "+f"(c[1]), "+f"(c[2]), "+f"(c[3])
                 : "r"(a[0]), "r"(a[1]), "r"(a[2]), "r"(a[3]), "r"(b0), "r"(b1));
}
__device__ __forceinline__ uint32_t pack_hi(float x, float y) {
    return (uint32_t)__bfloat16_as_ushort(__float2bfloat16(x)) |
           ((uint32_t)__bfloat16_as_ushort(__float2bfloat16(y)) << 16);
}
__device__ __forceinline__ uint32_t pack_lo(float x, float y) {
    float rx = x - __bfloat162float(__float2bfloat16(x));
    float ry = y - __bfloat162float(__float2bfloat16(y));
    return (uint32_t)__bfloat16_as_ushort(__float2bfloat16(rx)) |
           ((uint32_t)__bfloat16_as_ushort(__float2bfloat16(ry)) << 16);
}

// ---------------- graph prep ----------------
__global__ void k_init_counts() {
    int i = blockIdx.x * blockDim.x + threadIdx.x;
    if (i < N_NODES) { g_deg_out[i] = 0; g_deg_in[i] = 0; }
}
__global__ void k_count_deg(const int* __restrict__ src, const int* __restrict__ dst) {
    int e = blockIdx.x * blockDim.x + threadIdx.x;
    if (e < N_EDGES) {
        atomicAdd(&g_deg_out[src[e]], 1);
        atomicAdd(&g_deg_in[dst[e]], 1);
    }
}
__global__ void k_scan1() {
    __shared__ int sh[SCAN_B];
    int i = blockIdx.x * SCAN_B + threadIdx.x;
    int v = (i < N_NODES) ? g_deg_in[i] : 0;
    sh[threadIdx.x] = v;
    __syncthreads();
#pragma unroll
    for (int o = 1; o < SCAN_B; o <<= 1) {
        int t = (threadIdx.x >= o) ? sh[threadIdx.x - o] : 0;
        __syncthreads();
        sh[threadIdx.x] += t;
        __syncthreads();
    }
    if (i < N_NODES) g_off[i] = sh[threadIdx.x] - v;
    if (threadIdx.x == SCAN_B - 1) g_part[blockIdx.x] = sh[SCAN_B - 1];
}
__global__ void k_scan2() {
    __shared__ int sh[512];
    int t = threadIdx.x;
    int v = (t < NBLK) ? g_part[t] : 0;
    sh[t] = v;
    __syncthreads();
#pragma unroll
    for (int o = 1; o < 512; o <<= 1) {
        int x = (t >= o) ? sh[t - o] : 0;
        __syncthreads();
        sh[t] += x;
        __syncthreads();
    }
    if (t < NBLK) g_part[t] = sh[t] - v;
}
__global__ void k_scan3_inv() {
    int i = blockIdx.x * SCAN_B + threadIdx.x;
    if (i < N_NODES) {
        int o = g_off[i] + g_part[blockIdx.x];
        g_off[i] = o;
        g_cur[i] = o;
        g_inv_out[i] = rsqrtf(fmaxf((float)g_deg_out[i], 1.0f));
        g_inv_in[i]  = rsqrtf(fmaxf((float)g_deg_in[i], 1.0f));
    }
    if (i == 0) g_off[N_NODES] = N_EDGES;
}
__global__ void k_bucket(const int* __restrict__ src, const int* __restrict__ dst) {
    int e = blockIdx.x * blockDim.x + threadIdx.x;
    if (e < N_EDGES) {
        int p = atomicAdd(&g_cur[dst[e]], 1);
        g_esrc[p] = src[e];
    }
}
// both layers' W [K,N] fp32 -> Bt [N,K] bf16 hi/lo
__global__ void k_prep_w2(const float* __restrict__ W1, const float* __restrict__ W2) {
    int i = blockIdx.x * blockDim.x + threadIdx.x;
    int layer = i >= DIM * DIM;
    int j = i - layer * DIM * DIM;
    if (i >= 2 * DIM * DIM) return;
    int n = j >> 8, k = j & 255;
    float v = layer ? W2[k * DIM + n] : W1[k * DIM + n];
    __nv_bfloat16 h = __float2bfloat16(v);
    float l = v - __bfloat162float(h);
    if (layer) { g_bt2_hi[j] = h; g_bt2_lo[j] = __float2bfloat16(l); }
    else       { g_bt1_hi[j] = h; g_bt1_lo[j] = __float2bfloat16(l); }
}

// ---------------- CSR gather + bf16 split ----------------
// One warp per node; lane owns float4 cols {4*lane, 4*lane+128}.
__global__ __launch_bounds__(256)
void k_gather(const float* __restrict__ feat) {
    int node = (blockIdx.x * blockDim.x + threadIdx.x) >> 5;
    int lane = threadIdx.x & 31;
    if (node >= N_NODES) return;
    int e0 = g_off[node], e1 = g_off[node + 1];

    float4 a0 = make_float4(0.f, 0.f, 0.f, 0.f);
    float4 a1 = a0;

    int e = e0;
    for (; e + 2 <= e1; e += 2) {
        int sA = g_esrc[e], sB = g_esrc[e + 1];
        float wA = g_inv_out[sA], wB = g_inv_out[sB];
        const float4* fA = (const float4*)(feat + (size_t)sA * DIM);
        const float4* fB = (const float4*)(feat + (size_t)sB * DIM);
        float4 vA0 = fA[lane], vA1 = fA[lane + 32];
        float4 vB0 = fB[lane], vB1 = fB[lane + 32];
        a0.x = fmaf(wA, vA0.x, a0.x); a0.y = fmaf(wA, vA0.y, a0.y);
        a0.z = fmaf(wA, vA0.z, a0.z); a0.w = fmaf(wA, vA0.w, a0.w);
        a1.x = fmaf(wA, vA1.x, a1.x); a1.y = fmaf(wA, vA1.y, a1.y);
        a1.z = fmaf(wA, vA1.z, a1.z); a1.w = fmaf(wA, vA1.w, a1.w);
        a0.x = fmaf(wB, vB0.x, a0.x); a0.y = fmaf(wB, vB0.y, a0.y);
        a0.z = fmaf(wB, vB0.z, a0.z); a0.w = fmaf(wB, vB0.w, a0.w);
        a1.x = fmaf(wB, vB1.x, a1.x); a1.y = fmaf(wB, vB1.y, a1.y);
        a1.z = fmaf(wB, vB1.z, a1.z); a1.w = fmaf(wB, vB1.w, a1.w);
    }
    if (e < e1) {
        int s = g_esrc[e];
        float w = g_inv_out[s];
        const float4* fr = (const float4*)(feat + (size_t)s * DIM);
        float4 v0 = fr[lane], v1 = fr[lane + 32];
        a0.x = fmaf(w, v0.x, a0.x); a0.y = fmaf(w, v0.y, a0.y);
        a0.z = fmaf(w, v0.z, a0.z); a0.w = fmaf(w, v0.w, a0.w);
        a1.x = fmaf(w, v1.x, a1.x); a1.y = fmaf(w, v1.y, a1.y);
        a1.z = fmaf(w, v1.z, a1.z); a1.w = fmaf(w, v1.w, a1.w);
    }
    // split + store bf16 hi/lo (cols 4*lane and 4*lane+128)
    size_t base = (size_t)node * DIM + lane * 4;
    *(uint2*)(g_a_hi + base)       = make_uint2(pack_hi(a0.x, a0.y), pack_hi(a0.z, a0.w));
    *(uint2*)(g_a_lo + base)       = make_uint2(pack_lo(a0.x, a0.y), pack_lo(a0.z, a0.w));
    *(uint2*)(g_a_hi + base + 128) = make_uint2(pack_hi(a1.x, a1.y), pack_hi(a1.z, a1.w));
    *(uint2*)(g_a_lo + base + 128) = make_uint2(pack_lo(a1.x, a1.y), pack_lo(a1.z, a1.w));
}

// ---------------- HMMA GEMM: out = relu(inv_in[i]*(A@W) + b) ----------------
// BM=128, BN=256, BK=64, 512 threads (16 warps, 2m x 8n, warp tile 64x32).
// Stage: [Ah 16K][Al 16K][Bh 32K][Bl 32K] = 96KB, x2 = 192KB. Pure cp.async.
#define TA 16384
#define OFF_B 32768
#define TB 32768
#define STAGE_B 98304

__global__ __launch_bounds__(512, 1)
void k_gemm_mma(const __nv_bfloat16* __restrict__ Bh_g,
                const __nv_bfloat16* __restrict__ Bl_g,
                const float* __restrict__ bias, float* __restrict__ out) {
    extern __shared__ char smem[];
    const uint32_t sb = smem_u32(smem);
    const int tid = threadIdx.x, lane = tid & 31, wid = tid >> 5;
    const int wm = wid >> 3, wn = wid & 7;
    const int row0 = blockIdx.x * 128;

    float acc[4][4][4];
#pragma unroll
    for (int i = 0; i < 4; i++)
#pragma unroll
        for (int j = 0; j < 4; j++)
#pragma unroll
            for (int k = 0; k < 4; k++) acc[i][j][k] = 0.f;

#define CPALL(s, c)                                                                 \
    {                                                                               \
        _Pragma("unroll")                                                           \
        for (int it = 0; it < 2; it++) {  /* A: 128 rows x 8 chunks /512 = 2 */     \
            int id = tid + it * 512;                                                \
            int r = id >> 3, pc = id & 7;                                           \
            uint32_t dst = sb + (s) * STAGE_B + r * 128 + ((pc ^ (r & 7)) << 4);    \
            size_t aoff = (size_t)(row0 + r) * DIM + (c) * 64 + pc * 8;             \
            cp16(dst, g_a_hi + aoff);                                               \
            cp16(dst + TA, g_a_lo + aoff);                                          \
        }                                                                           \
        _Pragma("unroll")                                                           \
        for (int it = 0; it < 4; it++) {  /* B: 256 rows x 8 chunks /512 = 4 */     \
            int id = tid + it * 512;                                                \
            int r = id >> 3, pc = id & 7;                                           \
            uint32_t dst = sb + (s) * STAGE_B + OFF_B + r * 128 + ((pc ^ (r & 7)) << 4); \
            size_t boff = (size_t)r * DIM + (c) * 64 + pc * 8;                      \
            cp16(dst, Bh_g + boff);                                                 \
            cp16(dst + TB, Bl_g + boff);                                            \
        }                                                                           \
        cp_commit();                                                                \
    }

    CPALL(0, 0);

#pragma unroll
    for (int c = 0; c < 4; c++) {
        const int s = c & 1;
        const uint32_t st = sb + s * STAGE_B;
        cp_wait0();
        __syncthreads();
        if (c < 3) CPALL(1 - s, c + 1);

#pragma unroll
        for (int k16 = 0; k16 < 4; k16++) {
            uint32_t ah[4][4], al[4][4];
#pragma unroll
            for (int fm = 0; fm < 4; fm++) {
                int row = wm * 64 + fm * 16 + (lane & 15);
                int kc = k16 * 2 + (lane >> 4);
                uint32_t a = st + row * 128 + ((kc ^ (row & 7)) << 4);
                ldm4(ah[fm], a);
                ldm4(al[fm], a + TA);
            }
            uint32_t bh[2][4], bl[2][4];
#pragma unroll
            for (int rg = 0; rg < 2; rg++) {
                int nrow = wn * 32 + rg * 16 + (lane & 7) + ((lane & 16) >> 1);
                int kc = k16 * 2 + ((lane >> 3) & 1);
                uint32_t a = st + OFF_B + nrow * 128 + ((kc ^ (nrow & 7)) << 4);
                ldm4(bh[rg], a);
                ldm4(bl[rg], a + TB);
            }
#pragma unroll
            for (int fm = 0; fm < 4; fm++)
#pragma unroll
                for (int fn = 0; fn < 4; fn++) {
                    int rg = fn >> 1, o = (fn & 1) * 2;
                    mma16816(acc[fm][fn], ah[fm], bh[rg][o], bh[rg][o + 1]);
                    mma16816(acc[fm][fn], ah[fm], bl[rg][o], bl[rg][o + 1]);
                    mma16816(acc[fm][fn], al[fm], bh[rg][o], bh[rg][o + 1]);
                }
        }
        __syncthreads();
    }

    // epilogue: dst-norm + bias + relu
#pragma unroll
    for (int fm = 0; fm < 4; fm++) {
        int mbase = row0 + wm * 64 + fm * 16 + (lane >> 2);
#pragma unroll
        for (int half = 0; half < 2; half++) {
            int row = mbase + half * 8;
            if (row >= N_NODES) continue;
            float sc = g_inv_in[row];
#pragma unroll
            for (int fn = 0; fn < 4; fn++) {
                int col = wn * 32 + fn * 8 + 2 * (lane & 3);
                float v0 = acc[fm][fn][half * 2 + 0];
                float v1 = acc[fm][fn][half * 2 + 1];
                float2 o;
                o.x = fmaxf(fmaf(v0, sc, bias[col]), 0.f);
                o.y = fmaxf(fmaf(v1, sc, bias[col + 1]), 0.f);
                *(float2*)(out + (size_t)row * DIM + col) = o;
            }
        }
    }
}

// ---------------- launch ----------------
extern "C" void kernel_launch(void* const* d_in, const int* in_sizes, int n_in,
                              void* d_out, int out_size) {
    const int*   src  = (const int*)d_in[0];
    const int*   dst  = (const int*)d_in[1];
    const float* feat = (const float*)d_in[2];
    const float* W1   = (const float*)d_in[3];
    const float* b1   = (const float*)d_in[4];
    const float* W2   = (const float*)d_in[5];
    const float* b2   = (const float*)d_in[6];
    float*       out  = (float*)d_out;

    float* h; cudaGetSymbolAddress((void**)&h, g_h);
    __nv_bfloat16 *bt1h, *bt1l, *bt2h, *bt2l;
    cudaGetSymbolAddress((void**)&bt1h, g_bt1_hi);
    cudaGetSymbolAddress((void**)&bt1l, g_bt1_lo);
    cudaGetSymbolAddress((void**)&bt2h, g_bt2_hi);
    cudaGetSymbolAddress((void**)&bt2l, g_bt2_lo);

    static int smem_set = 0;
    if (!smem_set) {
        cudaFuncSetAttribute(k_gemm_mma, cudaFuncAttributeMaxDynamicSharedMemorySize,
                             2 * STAGE_B);
        smem_set = 1;
    }

    const int T = 256;
    const int gemm_grid = (N_NODES + 127) / 128;
    const int gather_grid = (N_NODES * 32 + T - 1) / T;

    // ---- prep ----
    k_init_counts<<<(N_NODES + T - 1) / T, T>>>();
    k_count_deg<<<(N_EDGES + T - 1) / T, T>>>(src, dst);
    k_scan1<<<NBLK, SCAN_B>>>();
    k_scan2<<<1, 512>>>();
    k_scan3_inv<<<NBLK, SCAN_B>>>();
    k_bucket<<<(N_EDGES + T - 1) / T, T>>>(src, dst);
    k_prep_w2<<<(2 * DIM * DIM + T - 1) / T, T>>>(W1, W2);

    // ---- layer 1 ----
    k_gather<<<gather_grid, T>>>(feat);
    k_gemm_mma<<<gemm_grid, 512, 2 * STAGE_B>>>(bt1h, bt1l, b1, h);

    // ---- layer 2 ----
    k_gather<<<gather_grid, T>>>(h);
    k_gemm_mma<<<gemm_grid, 512, 2 * STAGE_B>>>(bt2h, bt2l, b2, out);
}

// round 7
// speedup vs baseline: 2.5258x; 1.0059x over previous
#include <cuda_runtime.h>
#include <cuda_bf16.h>
#include <cstdint>

#define N_NODES 100000
#define N_EDGES 320000
#define DIM 256
#define PAD_ROWS 128

#define SCAN_B 256
#define NBLK ((N_NODES + SCAN_B - 1) / SCAN_B)

// ---------------- scratch (no allocations allowed) ----------------
__device__ int   g_deg_out[N_NODES];
__device__ int   g_deg_in[N_NODES];
__device__ float g_inv_out[N_NODES];
__device__ float g_inv_in[N_NODES];
__device__ float g_h[(size_t)N_NODES * DIM];
// gather output, pre-split bf16 (padded so full GEMM tiles read in-bounds)
__device__ __nv_bfloat16 g_a_hi[(size_t)(N_NODES + PAD_ROWS) * DIM];
__device__ __nv_bfloat16 g_a_lo[(size_t)(N_NODES + PAD_ROWS) * DIM];
// CSR (by dst)
__device__ int g_off[N_NODES + 1];
__device__ int g_cur[N_NODES];
__device__ int g_part[NBLK];
__device__ int g_esrc[N_EDGES];
// W transposed to [N,K], bf16 hi/lo
__device__ __nv_bfloat16 g_bt1_hi[DIM * DIM];
__device__ __nv_bfloat16 g_bt1_lo[DIM * DIM];
__device__ __nv_bfloat16 g_bt2_hi[DIM * DIM];
__device__ __nv_bfloat16 g_bt2_lo[DIM * DIM];

// ---------------- helpers ----------------
__device__ __forceinline__ uint32_t smem_u32(const void* p) {
    uint32_t a;
    asm("{ .reg .u64 t; cvta.to.shared.u64 t, %1; cvt.u32.u64 %0, t; }" : "=r"(a) : "l"(p));
    return a;
}
__device__ __forceinline__ void cp16(uint32_t dst, const void* src) {
    asm volatile("cp.async.cg.shared.global [%0], [%1], 16;"
                 :: "r"(dst), "l"(src) : "memory");
}
__device__ __forceinline__ void cp_commit() {
    asm volatile("cp.async.commit_group;" ::: "memory");
}
__device__ __forceinline__ void cp_wait0() {
    asm volatile("cp.async.wait_group 0;" ::: "memory");
}
__device__ __forceinline__ void ldm4(uint32_t* r, uint32_t addr) {
    asm volatile("ldmatrix.sync.aligned.m8n8.x4.shared.b16 {%0,%1,%2,%3}, [%4];"
                 : "=r"(r[0]), "=r"(r[1]), "=r"(r[2]), "=r"(r[3]) : "r"(addr));
}
__device__ __forceinline__ void mma16816(float* c, const uint32_t* a, uint32_t b0, uint32_t b1) {
    asm volatile("mma.sync.aligned.m16n8k16.row.col.f32.bf16.bf16.f32 "
                 "{%0,%1,%2,%3}, {%4,%5,%6,%7}, {%8,%9}, {%0,%1,%2,%3};"
                 : "+f"(c[0]), "+f"(c[1]), "+f"(c[2]), "+f"(c[3])
                 : "r"(a[0]), "r"(a[1]), "r"(a[2]), "r"(a[3]), "r"(b0), "r"(b1));
}
__device__ __forceinline__ uint32_t pack_hi(float x, float y) {
    return (uint32_t)__bfloat16_as_ushort(__float2bfloat16(x)) |
           ((uint32_t)__bfloat16_as_ushort(__float2bfloat16(y)) << 16);
}
__device__ __forceinline__ uint32_t pack_lo(float x, float y) {
    float rx = x - __bfloat162float(__float2bfloat16(x));
    float ry = y - __bfloat162float(__float2bfloat16(y));
    return (uint32_t)__bfloat16_as_ushort(__float2bfloat16(rx)) |
           ((uint32_t)__bfloat16_as_ushort(__float2bfloat16(ry)) << 16);
}
__device__ __forceinline__ void st_cs_u2(void* p, uint2 v) {
    asm volatile("st.global.cs.v2.u32 [%0], {%1, %2};"
                 :: "l"(p), "r"(v.x), "r"(v.y) : "memory");
}
__device__ __forceinline__ void fma4(float4& a, float w, const float4& v) {
    a.x = fmaf(w, v.x, a.x); a.y = fmaf(w, v.y, a.y);
    a.z = fmaf(w, v.z, a.z); a.w = fmaf(w, v.w, a.w);
}

// ---------------- graph prep ----------------
__global__ void k_init_counts() {
    int i = blockIdx.x * blockDim.x + threadIdx.x;
    if (i < N_NODES) { g_deg_out[i] = 0; g_deg_in[i] = 0; }
}
__global__ void k_count_deg(const int* __restrict__ src, const int* __restrict__ dst) {
    int e = blockIdx.x * blockDim.x + threadIdx.x;
    if (e < N_EDGES) {
        atomicAdd(&g_deg_out[src[e]], 1);
        atomicAdd(&g_deg_in[dst[e]], 1);
    }
}
__global__ void k_scan1() {
    __shared__ int sh[SCAN_B];
    int i = blockIdx.x * SCAN_B + threadIdx.x;
    int v = (i < N_NODES) ? g_deg_in[i] : 0;
    sh[threadIdx.x] = v;
    __syncthreads();
#pragma unroll
    for (int o = 1; o < SCAN_B; o <<= 1) {
        int t = (threadIdx.x >= o) ? sh[threadIdx.x - o] : 0;
        __syncthreads();
        sh[threadIdx.x] += t;
        __syncthreads();
    }
    if (i < N_NODES) g_off[i] = sh[threadIdx.x] - v;
    if (threadIdx.x == SCAN_B - 1) g_part[blockIdx.x] = sh[SCAN_B - 1];
}
__global__ void k_scan2() {
    __shared__ int sh[512];
    int t = threadIdx.x;
    int v = (t < NBLK) ? g_part[t] : 0;
    sh[t] = v;
    __syncthreads();
#pragma unroll
    for (int o = 1; o < 512; o <<= 1) {
        int x = (t >= o) ? sh[t - o] : 0;
        __syncthreads();
        sh[t] += x;
        __syncthreads();
    }
    if (t < NBLK) g_part[t] = sh[t] - v;
}
__global__ void k_scan3_inv() {
    int i = blockIdx.x * SCAN_B + threadIdx.x;
    if (i < N_NODES) {
        int o = g_off[i] + g_part[blockIdx.x];
        g_off[i] = o;
        g_cur[i] = o;
        g_inv_out[i] = rsqrtf(fmaxf((float)g_deg_out[i], 1.0f));
        g_inv_in[i]  = rsqrtf(fmaxf((float)g_deg_in[i], 1.0f));
    }
    if (i == 0) g_off[N_NODES] = N_EDGES;
}
__global__ void k_bucket(const int* __restrict__ src, const int* __restrict__ dst) {
    int e = blockIdx.x * blockDim.x + threadIdx.x;
    if (e < N_EDGES) {
        int p = atomicAdd(&g_cur[dst[e]], 1);
        g_esrc[p] = src[e];
    }
}
// both layers' W [K,N] fp32 -> Bt [N,K] bf16 hi/lo
__global__ void k_prep_w2(const float* __restrict__ W1, const float* __restrict__ W2) {
    int i = blockIdx.x * blockDim.x + threadIdx.x;
    int layer = i >= DIM * DIM;
    int j = i - layer * DIM * DIM;
    if (i >= 2 * DIM * DIM) return;
    int n = j >> 8, k = j & 255;
    float v = layer ? W2[k * DIM + n] : W1[k * DIM + n];
    __nv_bfloat16 h = __float2bfloat16(v);
    float l = v - __bfloat162float(h);
    if (layer) { g_bt2_hi[j] = h; g_bt2_lo[j] = __float2bfloat16(l); }
    else       { g_bt1_hi[j] = h; g_bt1_lo[j] = __float2bfloat16(l); }
}

// ---------------- CSR gather + bf16 split ----------------
// One warp per node; lane owns float4 cols {4*lane, 4*lane+128}.
// 4-edge batches: all indices, then all 32 row-loads in flight, then accumulate.
__global__ __launch_bounds__(256)
void k_gather(const float* __restrict__ feat) {
    int node = (blockIdx.x * blockDim.x + threadIdx.x) >> 5;
    int lane = threadIdx.x & 31;
    if (node >= N_NODES) return;
    int e0 = g_off[node], e1 = g_off[node + 1];

    float4 a0 = make_float4(0.f, 0.f, 0.f, 0.f);
    float4 a1 = a0;

    int e = e0;
    for (; e + 4 <= e1; e += 4) {
        int   s0 = g_esrc[e],     s1 = g_esrc[e + 1];
        int   s2 = g_esrc[e + 2], s3 = g_esrc[e + 3];
        float w0 = g_inv_out[s0], w1 = g_inv_out[s1];
        float w2 = g_inv_out[s2], w3 = g_inv_out[s3];
        const float4* f0 = (const float4*)(feat + (size_t)s0 * DIM);
        const float4* f1 = (const float4*)(feat + (size_t)s1 * DIM);
        const float4* f2 = (const float4*)(feat + (size_t)s2 * DIM);
        const float4* f3 = (const float4*)(feat + (size_t)s3 * DIM);
        float4 v00 = f0[lane], v01 = f0[lane + 32];
        float4 v10 = f1[lane], v11 = f1[lane + 32];
        float4 v20 = f2[lane], v21 = f2[lane + 32];
        float4 v30 = f3[lane], v31 = f3[lane + 32];
        fma4(a0, w0, v00); fma4(a1, w0, v01);
        fma4(a0, w1, v10); fma4(a1, w1, v11);
        fma4(a0, w2, v20); fma4(a1, w2, v21);
        fma4(a0, w3, v30); fma4(a1, w3, v31);
    }
    for (; e + 2 <= e1; e += 2) {
        int   sA = g_esrc[e], sB = g_esrc[e + 1];
        float wA = g_inv_out[sA], wB = g_inv_out[sB];
        const float4* fA = (const float4*)(feat + (size_t)sA * DIM);
        const float4* fB = (const float4*)(feat + (size_t)sB * DIM);
        float4 vA0 = fA[lane], vA1 = fA[lane + 32];
        float4 vB0 = fB[lane], vB1 = fB[lane + 32];
        fma4(a0, wA, vA0); fma4(a1, wA, vA1);
        fma4(a0, wB, vB0); fma4(a1, wB, vB1);
    }
    if (e < e1) {
        int s = g_esrc[e];
        float w = g_inv_out[s];
        const float4* fr = (const float4*)(feat + (size_t)s * DIM);
        float4 v0 = fr[lane], v1 = fr[lane + 32];
        fma4(a0, w, v0); fma4(a1, w, v1);
    }
    // split + store bf16 hi/lo (streaming: consumed once by GEMM, keep L2 for feat)
    size_t base = (size_t)node * DIM + lane * 4;
    st_cs_u2(g_a_hi + base,       make_uint2(pack_hi(a0.x, a0.y), pack_hi(a0.z, a0.w)));
    st_cs_u2(g_a_lo + base,       make_uint2(pack_lo(a0.x, a0.y), pack_lo(a0.z, a0.w)));
    st_cs_u2(g_a_hi + base + 128, make_uint2(pack_hi(a1.x, a1.y), pack_hi(a1.z, a1.w)));
    st_cs_u2(g_a_lo + base + 128, make_uint2(pack_lo(a1.x, a1.y), pack_lo(a1.z, a1.w)));
}

// ---------------- HMMA GEMM: out = relu(inv_in[i]*(A@W) + b) ----------------
// BM=128, BN=256, BK=64, 512 threads (16 warps, 2m x 8n, warp tile 64x32).
// Stage: [Ah 16K][Al 16K][Bh 32K][Bl 32K] = 96KB, x2 = 192KB. Pure cp.async.
#define TA 16384
#define OFF_B 32768
#define TB 32768
#define STAGE_B 98304

__global__ __launch_bounds__(512, 1)
void k_gemm_mma(const __nv_bfloat16* __restrict__ Bh_g,
                const __nv_bfloat16* __restrict__ Bl_g,
                const float* __restrict__ bias, float* __restrict__ out) {
    extern __shared__ char smem[];
    const uint32_t sb = smem_u32(smem);
    const int tid = threadIdx.x, lane = tid & 31, wid = tid >> 5;
    const int wm = wid >> 3, wn = wid & 7;
    const int row0 = blockIdx.x * 128;

    float acc[4][4][4];
#pragma unroll
    for (int i = 0; i < 4; i++)
#pragma unroll
        for (int j = 0; j < 4; j++)
#pragma unroll
            for (int k = 0; k < 4; k++) acc[i][j][k] = 0.f;

#define CPALL(s, c)                                                                 \
    {                                                                               \
        _Pragma("unroll")                                                           \
        for (int it = 0; it < 2; it++) {                                            \
            int id = tid + it * 512;                                                \
            int r = id >> 3, pc = id & 7;                                           \
            uint32_t dst = sb + (s) * STAGE_B + r * 128 + ((pc ^ (r & 7)) << 4);    \
            size_t aoff = (size_t)(row0 + r) * DIM + (c) * 64 + pc * 8;             \
            cp16(dst, g_a_hi + aoff);                                               \
            cp16(dst + TA, g_a_lo + aoff);                                          \
        }                                                                           \
        _Pragma("unroll")                                                           \
        for (int it = 0; it < 4; it++) {                                            \
            int id = tid + it * 512;                                                \
            int r = id >> 3, pc = id & 7;                                           \
            uint32_t dst = sb + (s) * STAGE_B + OFF_B + r * 128 + ((pc ^ (r & 7)) << 4); \
            size_t boff = (size_t)r * DIM + (c) * 64 + pc * 8;                      \
            cp16(dst, Bh_g + boff);                                                 \
            cp16(dst + TB, Bl_g + boff);                                            \
        }                                                                           \
        cp_commit();                                                                \
    }

    CPALL(0, 0);

#pragma unroll
    for (int c = 0; c < 4; c++) {
        const int s = c & 1;
        const uint32_t st = sb + s * STAGE_B;
        cp_wait0();
        __syncthreads();
        if (c < 3) CPALL(1 - s, c + 1);

#pragma unroll
        for (int k16 = 0; k16 < 4; k16++) {
            uint32_t ah[4][4], al[4][4];
#pragma unroll
            for (int fm = 0; fm < 4; fm++) {
                int row = wm * 64 + fm * 16 + (lane & 15);
                int kc = k16 * 2 + (lane >> 4);
                uint32_t a = st + row * 128 + ((kc ^ (row & 7)) << 4);
                ldm4(ah[fm], a);
                ldm4(al[fm], a + TA);
            }
            uint32_t bh[2][4], bl[2][4];
#pragma unroll
            for (int rg = 0; rg < 2; rg++) {
                int nrow = wn * 32 + rg * 16 + (lane & 7) + ((lane & 16) >> 1);
                int kc = k16 * 2 + ((lane >> 3) & 1);
                uint32_t a = st + OFF_B + nrow * 128 + ((kc ^ (nrow & 7)) << 4);
                ldm4(bh[rg], a);
                ldm4(bl[rg], a + TB);
            }
#pragma unroll
            for (int fm = 0; fm < 4; fm++)
#pragma unroll
                for (int fn = 0; fn < 4; fn++) {
                    int rg = fn >> 1, o = (fn & 1) * 2;
                    mma16816(acc[fm][fn], ah[fm], bh[rg][o], bh[rg][o + 1]);
                    mma16816(acc[fm][fn], ah[fm], bl[rg][o], bl[rg][o + 1]);
                    mma16816(acc[fm][fn], al[fm], bh[rg][o], bh[rg][o + 1]);
                }
        }
        __syncthreads();
    }

    // epilogue: dst-norm + bias + relu
#pragma unroll
    for (int fm = 0; fm < 4; fm++) {
        int mbase = row0 + wm * 64 + fm * 16 + (lane >> 2);
#pragma unroll
        for (int half = 0; half < 2; half++) {
            int row = mbase + half * 8;
            if (row >= N_NODES) continue;
            float sc = g_inv_in[row];
#pragma unroll
            for (int fn = 0; fn < 4; fn++) {
                int col = wn * 32 + fn * 8 + 2 * (lane & 3);
                float v0 = acc[fm][fn][half * 2 + 0];
                float v1 = acc[fm][fn][half * 2 + 1];
                float2 o;
                o.x = fmaxf(fmaf(v0, sc, bias[col]), 0.f);
                o.y = fmaxf(fmaf(v1, sc, bias[col + 1]), 0.f);
                *(float2*)(out + (size_t)row * DIM + col) = o;
            }
        }
    }
}

// ---------------- launch ----------------
extern "C" void kernel_launch(void* const* d_in, const int* in_sizes, int n_in,
                              void* d_out, int out_size) {
    const int*   src  = (const int*)d_in[0];
    const int*   dst  = (const int*)d_in[1];
    const float* feat = (const float*)d_in[2];
    const float* W1   = (const float*)d_in[3];
    const float* b1   = (const float*)d_in[4];
    const float* W2   = (const float*)d_in[5];
    const float* b2   = (const float*)d_in[6];
    float*       out  = (float*)d_out;

    float* h; cudaGetSymbolAddress((void**)&h, g_h);
    __nv_bfloat16 *bt1h, *bt1l, *bt2h, *bt2l;
    cudaGetSymbolAddress((void**)&bt1h, g_bt1_hi);
    cudaGetSymbolAddress((void**)&bt1l, g_bt1_lo);
    cudaGetSymbolAddress((void**)&bt2h, g_bt2_hi);
    cudaGetSymbolAddress((void**)&bt2l, g_bt2_lo);

    static int smem_set = 0;
    if (!smem_set) {
        cudaFuncSetAttribute(k_gemm_mma, cudaFuncAttributeMaxDynamicSharedMemorySize,
                             2 * STAGE_B);
        smem_set = 1;
    }

    const int T = 256;
    const int gemm_grid = (N_NODES + 127) / 128;
    const int gather_grid = (N_NODES * 32 + T - 1) / T;

    // ---- prep ----
    k_init_counts<<<(N_NODES + T - 1) / T, T>>>();
    k_count_deg<<<(N_EDGES + T - 1) / T, T>>>(src, dst);
    k_scan1<<<NBLK, SCAN_B>>>();
    k_scan2<<<1, 512>>>();
    k_scan3_inv<<<NBLK, SCAN_B>>>();
    k_bucket<<<(N_EDGES + T - 1) / T, T>>>(src, dst);
    k_prep_w2<<<(2 * DIM * DIM + T - 1) / T, T>>>(W1, W2);

    // ---- layer 1 ----
    k_gather<<<gather_grid, T>>>(feat);
    k_gemm_mma<<<gemm_grid, 512, 2 * STAGE_B>>>(bt1h, bt1l, b1, h);

    // ---- layer 2 ----
    k_gather<<<gather_grid, T>>>(h);
    k_gemm_mma<<<gemm_grid, 512, 2 * STAGE_B>>>(bt2h, bt2l, b2, out);
}